// round 8
// baseline (speedup 1.0000x reference)
#include <cuda_runtime.h>
#include <math.h>

#define NFFT   1024
#define HOP    256
#define NFR    16384
#define NB     513
#define LX     4194304
#define OUTLEN 4194048
#define SCAN_M 4096
#define NBLK   1024

__device__ float  g_saw[LX];
__device__ float  g_pulse[LX];
__device__ float  g_envnoiT[(size_t)NFR * NB];
__device__ float  g_envperT[(size_t)NFR * NB];
__device__ float  g_frames[(size_t)NFR * NFFT];
__device__ float  g_bsum[NBLK];
__device__ float  g_bpref[NBLK];
__device__ float2 g_tw512[256];
__device__ float2 g_tw1024[513];
__device__ float  g_win[NFFT];

__global__ void k_init() {
    int i = blockIdx.x * blockDim.x + threadIdx.x;
    if (i < 256) {
        double th = 2.0 * 3.14159265358979323846 * (double)i / 512.0;
        g_tw512[i] = make_float2((float)cos(th), (float)sin(th));
    }
    if (i < 513) {
        double th = 2.0 * 3.14159265358979323846 * (double)i / 1024.0;
        g_tw1024[i] = make_float2((float)cos(th), (float)sin(th));
    }
    if (i < NFFT) {
        float ang = __fmul_rn(__fmul_rn(6.28318530717958647692f, (float)i), 0.0009765625f);
        g_win[i] = 0.5f * (1.0f - cosf(ang));
    }
}

__global__ void k_transpose(const float* __restrict__ in, float* __restrict__ out, int doexp) {
    __shared__ float tile[32][33];
    int tx = threadIdx.x, ty = threadIdx.y;
    int t0 = blockIdx.x * 32, k0 = blockIdx.y * 32;
    for (int r = ty; r < 32; r += 8) {
        int k = k0 + r;
        tile[r][tx] = (k < NB) ? in[(size_t)k * NFR + t0 + tx] : 0.0f;
    }
    __syncthreads();
    for (int r = ty; r < 32; r += 8) {
        int t = t0 + r, k = k0 + tx;
        if (k < NB) {
            float v = tile[tx][r];
            out[(size_t)t * NB + k] = doexp ? expf(v) : v;
        }
    }
}

__device__ __forceinline__ float f0_up_val(const float* __restrict__ lf, int i) {
    float fi  = (float)i;
    float pos = __fmul_rn(__fadd_rn(fi, 0.5f), 0.00390625f);
    pos = __fsub_rn(pos, 0.5f);
    pos = fminf(fmaxf(pos, 0.0f), 16383.0f);
    float fl  = floorf(pos);
    int lo = (int)fl;
    int hi = min(lo + 1, NFR - 1);
    float frac = __fsub_rn(pos, fl);
    float a = expf(__ldg(lf + lo));
    float b = expf(__ldg(lf + hi));
    return __fadd_rn(__fmul_rn(a, __fsub_rn(1.0f, frac)), __fmul_rn(b, frac));
}

#define LVOFF(k)  (SCAN_M - (SCAN_M >> ((k) - 1)))
#define LVOFFM(k) (NBLK - (NBLK >> ((k) - 1)))

__device__ __forceinline__ void upsweep4096(const float* sx, float* slev, int tid) {
    for (int i = tid; i < 2048; i += 512) slev[i] = sx[2 * i] + sx[2 * i + 1];
    __syncthreads();
    for (int k = 2; k <= 12; k++) {
        int len = SCAN_M >> k;
        int off = LVOFF(k), offp = LVOFF(k - 1);
        for (int i = tid; i < len; i += 512)
            slev[off + i] = slev[offp + 2 * i] + slev[offp + 2 * i + 1];
        __syncthreads();
    }
}

__global__ __launch_bounds__(512) void k_scan_up(const float* __restrict__ lf) {
    __shared__ float sx[SCAN_M];
    __shared__ float slev[SCAN_M - 1];
    int tid = threadIdx.x, base = blockIdx.x * SCAN_M;
    for (int i = tid; i < SCAN_M; i += 512) sx[i] = f0_up_val(lf, base + i);
    __syncthreads();
    upsweep4096(sx, slev, tid);
    if (tid == 0) g_bsum[blockIdx.x] = slev[SCAN_M - 2];
}

__global__ __launch_bounds__(512) void k_scan_mid() {
    __shared__ float sx[NBLK];
    __shared__ float slev[NBLK - 1];
    int tid = threadIdx.x;
    for (int i = tid; i < NBLK; i += 512) sx[i] = g_bsum[i];
    __syncthreads();
    for (int i = tid; i < 512; i += 512) slev[i] = sx[2 * i] + sx[2 * i + 1];
    __syncthreads();
    for (int k = 2; k <= 10; k++) {
        int len = NBLK >> k;
        int off = LVOFFM(k), offp = LVOFFM(k - 1);
        for (int i = tid; i < len; i += 512)
            slev[off + i] = slev[offp + 2 * i] + slev[offp + 2 * i + 1];
        __syncthreads();
    }
    for (int k = 9; k >= 1; k--) {
        int len = NBLK >> k;
        int off = LVOFFM(k), offn = LVOFFM(k + 1);
        for (int i = tid; i < len; i += 512) {
            float v;
            if (i & 1)      v = slev[offn + ((i - 1) >> 1)];
            else if (i)     v = slev[offn + (i >> 1) - 1] + slev[off + i];
            else            v = slev[off];
            slev[off + i] = v;
        }
        __syncthreads();
    }
    for (int i = tid; i < NBLK; i += 512) {
        float v;
        if (i & 1)      v = slev[(i - 1) >> 1];
        else if (i)     v = slev[(i >> 1) - 1] + sx[i];
        else            v = sx[0];
        g_bpref[i] = v;
    }
}

__global__ __launch_bounds__(512) void k_scan_down(const float* __restrict__ lf) {
    __shared__ float sx[SCAN_M];
    __shared__ float slev[SCAN_M - 1];
    int tid = threadIdx.x, b = blockIdx.x, base = b * SCAN_M;
    float carry = (b == 0) ? 0.0f : g_bpref[b - 1];
    for (int i = tid; i < SCAN_M; i += 512) sx[i] = f0_up_val(lf, base + i);
    __syncthreads();
    upsweep4096(sx, slev, tid);
    if (tid == 0) slev[SCAN_M - 2] = g_bpref[b];   // S_12 = mid-scan prefix (bit-exact copy)
    __syncthreads();
    for (int k = 11; k >= 1; k--) {
        int len = SCAN_M >> k;
        int off = LVOFF(k), offn = LVOFF(k + 1);
        for (int i = tid; i < len; i += 512) {
            float v;
            if (i & 1)      v = slev[offn + ((i - 1) >> 1)];
            else if (i)     v = slev[offn + (i >> 1) - 1] + slev[off + i];
            else            v = b ? (carry + slev[off]) : slev[off];
            slev[off + i] = v;
        }
        __syncthreads();
    }
    for (int i = tid; i < SCAN_M; i += 512) {
        float v;
        if (i & 1)      v = slev[(i - 1) >> 1];
        else if (i)     v = slev[(i >> 1) - 1] + sx[i];
        else            v = b ? (carry + sx[0]) : sx[0];
        float ph = v / 24000.0f;
        g_saw[base + i] = __fsub_rn(ph, truncf(ph));
    }
}

__global__ void k_pulse(const float* __restrict__ lf) {
    int i = blockIdx.x * blockDim.x + threadIdx.x;
    if (i >= LX) return;
    float s0 = g_saw[i];
    float s1 = g_saw[(i + 1 == LX) ? 0 : (i + 1)];
    float fu = f0_up_val(lf, i);
    g_pulse[i] = __fadd_rn(__fsub_rn(s0, s1), fu / 24000.0f);
}

__device__ __forceinline__ int reflect_idx(int p) {
    if (p < 0) return -p;
    if (p >= LX) return 2 * LX - 2 - p;
    return p;
}

// Stockham complex FFT-512, 128 threads, result in returned buffer.
__device__ float2* fft512(float2* x, float2* y, const float2* tw, int tid, int inv) {
    float2* s = x; float2* d = y;
    #pragma unroll
    for (int st = 0; st < 9; st++) {
        int str = 1 << st;
        #pragma unroll
        for (int tt = 0; tt < 2; tt++) {
            int t = tid + tt * 128;
            int p = t >> st;
            int q = t & (str - 1);
            float2 a = s[q + str * p];
            float2 b = s[q + str * p + 256];
            float2 w = tw[t & ~(str - 1)];
            float2 sum = make_float2(a.x + b.x, a.y + b.y);
            float2 df  = make_float2(a.x - b.x, a.y - b.y);
            float2 r;
            if (inv > 0) r = make_float2(df.x * w.x - df.y * w.y, df.y * w.x + df.x * w.y);
            else         r = make_float2(df.x * w.x + df.y * w.y, df.y * w.x - df.x * w.y);
            d[q + 2 * str * p] = sum;
            d[q + 2 * str * p + str] = r;
        }
        __syncthreads();
        float2* tmp = s; s = d; d = tmp;
    }
    return s;
}

__global__ __launch_bounds__(128) void k_frames(const float* __restrict__ noise) {
    __shared__ float2 bufA[512], bufB[512];
    __shared__ float2 FC[513];
    __shared__ float  sA[513];
    __shared__ float2 twS[256];
    __shared__ float  winS[1024];
    int tid = threadIdx.x, b = blockIdx.x;
    const float s512 = 1.0f / 512.0f;

    for (int i = tid; i < 256; i += 128) twS[i] = g_tw512[i];
    for (int i = tid; i < 1024; i += 128) winS[i] = g_win[i];
    for (int k = tid; k <= 512; k += 128) sA[k] = g_envperT[(size_t)b * NB + k];
    __syncthreads();

    // ---- min-phase: irfft of real log-amp A (pack into complex-512) ----
    for (int k = tid; k < 512; k += 128) {
        float u = sA[k], v = sA[512 - k];
        float2 tw = g_tw1024[k];
        float a  = 0.5f * (u + v);
        float dr = 0.5f * (u - v);
        bufA[k] = make_float2(a - dr * tw.y, dr * tw.x);
    }
    __syncthreads();
    float2* z = fft512(bufA, bufB, twS, tid, +1);      // cepstrum pairs (unscaled)
    float2* o = (z == bufA) ? bufB : bufA;
    for (int n = tid; n < 512; n += 128) {             // fold + pack (1/512 folded in)
        float2 zv = z[n];
        float2 w;
        if (n == 0)        w = make_float2(zv.x * s512, 2.0f * zv.y * s512);
        else if (n < 256)  w = make_float2(2.0f * zv.x * s512, 2.0f * zv.y * s512);
        else if (n == 256) w = make_float2(zv.x * s512, 0.0f);
        else               w = make_float2(0.0f, 0.0f);
        o[n] = w;
    }
    __syncthreads();
    float2* W = fft512(o, z, twS, tid, -1);            // rfft(folded cep) packed
    for (int k = tid; k <= 512; k += 128) {            // unpack H, F = exp(H)
        float2 u = W[k & 511], v = W[(512 - k) & 511];
        float2 tw = g_tw1024[k];
        float ar = 0.5f * (u.x + v.x), ai = 0.5f * (u.y - v.y);
        float dr = u.x - v.x, di = u.y + v.y;
        float er = 0.5f * di, ei = -0.5f * dr;
        float hr = ar + er * tw.x + ei * tw.y;
        float hi = ai + ei * tw.x - er * tw.y;
        float m = expf(hr);
        FC[k] = make_float2(m * cosf(hi), m * sinf(hi));
    }
    for (int k = tid; k <= 512; k += 128) sA[k] = g_envnoiT[(size_t)b * NB + k];
    __syncthreads();

    // ---- pulse frame rfft, multiply by min-phase F ----
    for (int n = tid; n < 512; n += 128) {
        int j0 = 2 * n, j1 = 2 * n + 1;
        float p0 = g_pulse[reflect_idx(b * 256 + j0 - 256)] * winS[j0];
        float p1 = g_pulse[reflect_idx(b * 256 + j1 - 256)] * winS[j1];
        bufA[n] = make_float2(p0, p1);
    }
    __syncthreads();
    float2* Zp = fft512(bufA, bufB, twS, tid, -1);
    for (int k = tid; k <= 512; k += 128) {
        float2 u = Zp[k & 511], v = Zp[(512 - k) & 511];
        float2 tw = g_tw1024[k];
        float ar = 0.5f * (u.x + v.x), ai = 0.5f * (u.y - v.y);
        float dr = u.x - v.x, di = u.y + v.y;
        float er = 0.5f * di, ei = -0.5f * dr;
        float sr = ar + er * tw.x + ei * tw.y;
        float si = ai + ei * tw.x - er * tw.y;
        float2 f = FC[k];
        FC[k] = make_float2(sr * f.x - si * f.y, sr * f.y + si * f.x);
    }
    __syncthreads();

    // ---- noise frame rfft, multiply by env, accumulate ----
    for (int n = tid; n < 512; n += 128) {
        int j0 = 2 * n, j1 = 2 * n + 1;
        float p0 = noise[reflect_idx(b * 256 + j0 - 256)] * winS[j0];
        float p1 = noise[reflect_idx(b * 256 + j1 - 256)] * winS[j1];
        bufA[n] = make_float2(p0, p1);
    }
    __syncthreads();
    float2* Zn = fft512(bufA, bufB, twS, tid, -1);
    for (int k = tid; k <= 512; k += 128) {
        float2 u = Zn[k & 511], v = Zn[(512 - k) & 511];
        float2 tw = g_tw1024[k];
        float ar = 0.5f * (u.x + v.x), ai = 0.5f * (u.y - v.y);
        float dr = u.x - v.x, di = u.y + v.y;
        float er = 0.5f * di, ei = -0.5f * dr;
        float sr = ar + er * tw.x + ei * tw.y;
        float si = ai + ei * tw.x - er * tw.y;
        float e = sA[k];
        float2 c = FC[k];
        FC[k] = make_float2(c.x + sr * e, c.y + si * e);
    }
    __syncthreads();

    // ---- irfft(C) -> windowed frame ----
    for (int k = tid; k < 512; k += 128) {
        float2 u = FC[k], v = FC[512 - k];
        float2 tw = g_tw1024[k];
        float xr = 0.5f * (u.x + v.x), xi = 0.5f * (u.y - v.y);
        float dr = 0.5f * (u.x - v.x), di = 0.5f * (u.y + v.y);
        float tr = dr * tw.x - di * tw.y;
        float ti = dr * tw.y + di * tw.x;
        bufA[k] = make_float2(xr - ti, xi + tr);
    }
    __syncthreads();
    float2* zz = fft512(bufA, bufB, twS, tid, +1);
    float* fr = g_frames + (size_t)b * 1024;
    for (int n = tid; n < 512; n += 128) {
        float2 zv = zz[n];
        fr[2 * n]     = zv.x * s512 * winS[2 * n];
        fr[2 * n + 1] = zv.y * s512 * winS[2 * n + 1];
    }
}

__global__ void k_ola(float* __restrict__ out) {
    int m = blockIdx.x * 256 + threadIdx.x;
    if (m >= OUTLEN) return;
    int q = m + 512;
    int imin = (q > 1023) ? ((q - 1023 + 255) >> 8) : 0;
    int imax = min(q >> 8, NFR - 1);
    float sig = 0.0f, ws = 0.0f;
    for (int i = imin; i <= imax; i++) {
        int j = q - (i << 8);
        sig += g_frames[(size_t)i * 1024 + j];
        float w = g_win[j];
        ws += w * w;
    }
    out[m] = sig / fmaxf(ws, 1e-11f);
}

extern "C" void kernel_launch(void* const* d_in, const int* in_sizes, int n_in,
                              void* d_out, int out_size) {
    const float* log_f0 = (const float*)d_in[0];
    const float* env_noi = (const float*)d_in[1];
    const float* env_per = (const float*)d_in[2];
    const float* noise = (const float*)d_in[3];
    float* out = (float*)d_out;

    float* envnoiT; cudaGetSymbolAddress((void**)&envnoiT, g_envnoiT);
    float* envperT; cudaGetSymbolAddress((void**)&envperT, g_envperT);

    k_init<<<8, 128>>>();
    dim3 tb(32, 8), tg(NFR / 32, (NB + 31) / 32);
    k_transpose<<<tg, tb>>>(env_noi, envnoiT, 1);
    k_transpose<<<tg, tb>>>(env_per, envperT, 0);
    k_scan_up<<<NBLK, 512>>>(log_f0);
    k_scan_mid<<<1, 512>>>();
    k_scan_down<<<NBLK, 512>>>(log_f0);
    k_pulse<<<LX / 256, 256>>>(log_f0);
    k_frames<<<NFR, 128>>>(noise);
    k_ola<<<(OUTLEN + 255) / 256, 256>>>(out);
}

// round 9
// speedup vs baseline: 1.0075x; 1.0075x over previous
#include <cuda_runtime.h>
#include <math.h>

#define NFFT   1024
#define HOP    256
#define NFR    16384
#define NB     513
#define LX     4194304
#define OUTLEN 4194048
#define SCAN_M 4096
#define NBLK   1024

__device__ float  g_pulse[LX];
__device__ float  g_envnoiT[(size_t)NFR * NB];
__device__ float  g_envperT[(size_t)NFR * NB];
__device__ float  g_frames[(size_t)NFR * NFFT];
__device__ float  g_bsum[NBLK];
__device__ float  g_bpref[NBLK];
__device__ float2 g_tw512[512];     // full circle e^{+2pi i k/512}
__device__ float2 g_tw1024[513];
__device__ float  g_win[NFFT];

__global__ void k_init() {
    int i = blockIdx.x * blockDim.x + threadIdx.x;
    if (i < 512) {
        double th = 2.0 * 3.14159265358979323846 * (double)i / 512.0;
        g_tw512[i] = make_float2((float)cos(th), (float)sin(th));
    }
    if (i < 513) {
        double th = 2.0 * 3.14159265358979323846 * (double)i / 1024.0;
        g_tw1024[i] = make_float2((float)cos(th), (float)sin(th));
    }
    if (i < NFFT) {
        float ang = __fmul_rn(__fmul_rn(6.28318530717958647692f, (float)i), 0.0009765625f);
        g_win[i] = 0.5f * (1.0f - cosf(ang));
    }
}

__global__ void k_transpose(const float* __restrict__ in, float* __restrict__ out, int doexp) {
    __shared__ float tile[32][33];
    int tx = threadIdx.x, ty = threadIdx.y;
    int t0 = blockIdx.x * 32, k0 = blockIdx.y * 32;
    for (int r = ty; r < 32; r += 8) {
        int k = k0 + r;
        tile[r][tx] = (k < NB) ? in[(size_t)k * NFR + t0 + tx] : 0.0f;
    }
    __syncthreads();
    for (int r = ty; r < 32; r += 8) {
        int t = t0 + r, k = k0 + tx;
        if (k < NB) {
            float v = tile[tx][r];
            out[(size_t)t * NB + k] = doexp ? expf(v) : v;
        }
    }
}

__device__ __forceinline__ float f0_up_val(const float* __restrict__ lf, int i) {
    float fi  = (float)i;
    float pos = __fmul_rn(__fadd_rn(fi, 0.5f), 0.00390625f);
    pos = __fsub_rn(pos, 0.5f);
    pos = fminf(fmaxf(pos, 0.0f), 16383.0f);
    float fl  = floorf(pos);
    int lo = (int)fl;
    int hi = min(lo + 1, NFR - 1);
    float frac = __fsub_rn(pos, fl);
    float a = expf(__ldg(lf + lo));
    float b = expf(__ldg(lf + hi));
    return __fadd_rn(__fmul_rn(a, __fsub_rn(1.0f, frac)), __fmul_rn(b, frac));
}

#define LVOFF(k)  (SCAN_M - (SCAN_M >> ((k) - 1)))
#define LVOFFM(k) (NBLK - (NBLK >> ((k) - 1)))

__device__ __forceinline__ void upsweep4096(const float* sx, float* slev, int tid) {
    for (int i = tid; i < 2048; i += 512) slev[i] = sx[2 * i] + sx[2 * i + 1];
    __syncthreads();
    for (int k = 2; k <= 12; k++) {
        int len = SCAN_M >> k;
        int off = LVOFF(k), offp = LVOFF(k - 1);
        for (int i = tid; i < len; i += 512)
            slev[off + i] = slev[offp + 2 * i] + slev[offp + 2 * i + 1];
        __syncthreads();
    }
}

__global__ __launch_bounds__(512) void k_scan_up(const float* __restrict__ lf) {
    __shared__ float sx[SCAN_M];
    __shared__ float slev[SCAN_M - 1];
    int tid = threadIdx.x, base = blockIdx.x * SCAN_M;
    for (int i = tid; i < SCAN_M; i += 512) sx[i] = f0_up_val(lf, base + i);
    __syncthreads();
    upsweep4096(sx, slev, tid);
    if (tid == 0) g_bsum[blockIdx.x] = slev[SCAN_M - 2];
}

__global__ __launch_bounds__(512) void k_scan_mid() {
    __shared__ float sx[NBLK];
    __shared__ float slev[NBLK - 1];
    int tid = threadIdx.x;
    for (int i = tid; i < NBLK; i += 512) sx[i] = g_bsum[i];
    __syncthreads();
    for (int i = tid; i < 512; i += 512) slev[i] = sx[2 * i] + sx[2 * i + 1];
    __syncthreads();
    for (int k = 2; k <= 10; k++) {
        int len = NBLK >> k;
        int off = LVOFFM(k), offp = LVOFFM(k - 1);
        for (int i = tid; i < len; i += 512)
            slev[off + i] = slev[offp + 2 * i] + slev[offp + 2 * i + 1];
        __syncthreads();
    }
    for (int k = 9; k >= 1; k--) {
        int len = NBLK >> k;
        int off = LVOFFM(k), offn = LVOFFM(k + 1);
        for (int i = tid; i < len; i += 512) {
            float v;
            if (i & 1)      v = slev[offn + ((i - 1) >> 1)];
            else if (i)     v = slev[offn + (i >> 1) - 1] + slev[off + i];
            else            v = slev[off];
            slev[off + i] = v;
        }
        __syncthreads();
    }
    for (int i = tid; i < NBLK; i += 512) {
        float v;
        if (i & 1)      v = slev[(i - 1) >> 1];
        else if (i)     v = slev[(i >> 1) - 1] + sx[i];
        else            v = sx[0];
        g_bpref[i] = v;
    }
}

// scan_down + pulse fused: writes g_pulse directly (g_saw eliminated)
__global__ __launch_bounds__(512) void k_scan_down(const float* __restrict__ lf) {
    __shared__ float sx[SCAN_M];
    __shared__ float slev[SCAN_M - 1];
    int tid = threadIdx.x, b = blockIdx.x, base = b * SCAN_M;
    float carry = (b == 0) ? 0.0f : g_bpref[b - 1];
    for (int i = tid; i < SCAN_M; i += 512) sx[i] = f0_up_val(lf, base + i);
    __syncthreads();
    upsweep4096(sx, slev, tid);
    if (tid == 0) slev[SCAN_M - 2] = g_bpref[b];   // S_12 = mid-scan prefix (bit-exact copy)
    __syncthreads();
    for (int k = 11; k >= 1; k--) {
        int len = SCAN_M >> k;
        int off = LVOFF(k), offn = LVOFF(k + 1);
        for (int i = tid; i < len; i += 512) {
            float v;
            if (i & 1)      v = slev[offn + ((i - 1) >> 1)];
            else if (i)     v = slev[offn + (i >> 1) - 1] + slev[off + i];
            else            v = b ? (carry + slev[off]) : slev[off];
            slev[off + i] = v;
        }
        __syncthreads();
    }
    for (int i = tid; i < SCAN_M; i += 512) {
        float vi;
        if (i & 1)      vi = slev[(i - 1) >> 1];
        else if (i)     vi = slev[(i >> 1) - 1] + sx[i];
        else            vi = b ? (carry + sx[0]) : sx[0];
        float vip;
        int j = i + 1;
        if (j < SCAN_M) {
            if (j & 1)  vip = slev[(j - 1) >> 1];
            else        vip = slev[(j >> 1) - 1] + sx[j];
        } else if (b < NBLK - 1) {
            vip = g_bpref[b] + f0_up_val(lf, base + SCAN_M);  // next block's i=0 formula
        } else {
            vip = f0_up_val(lf, 0);                           // roll to global index 0
        }
        float ph0 = vi / 24000.0f;  float sw0 = __fsub_rn(ph0, truncf(ph0));
        float ph1 = vip / 24000.0f; float sw1 = __fsub_rn(ph1, truncf(ph1));
        g_pulse[base + i] = __fadd_rn(__fsub_rn(sw0, sw1), sx[i] / 24000.0f);
    }
}

__device__ __forceinline__ int reflect_idx(int p) {
    if (p < 0) return -p;
    if (p >= LX) return 2 * LX - 2 - p;
    return p;
}

// ---------------- radix-4 Stockham FFT-512, 128 threads ----------------
#define IDX(a) ((a) + ((a) >> 3))
#define FFTBUF 576   // 512 + 64 padding

__device__ __forceinline__ float2 cmul_fwd(float2 a, float2 w) {  // a * e^{-i th}
    return make_float2(a.x * w.x + a.y * w.y, a.y * w.x - a.x * w.y);
}
__device__ __forceinline__ float2 cmul_inv(float2 a, float2 w) {  // a * e^{+i th}
    return make_float2(a.x * w.x - a.y * w.y, a.y * w.x + a.x * w.y);
}

template <int INV>
__device__ float2* fft512(float2* x, float2* y, const float2* tw, int tid) {
    float2* s = x; float2* d = y;
    int str = 1;
    #pragma unroll
    for (int stg = 0; stg < 4; stg++) {           // radix-4: str = 1,4,16,64
        int q  = tid & (str - 1);
        int pb = tid - q;                          // p * str
        float2 a0 = s[IDX(tid)];
        float2 a1 = s[IDX(tid + 128)];
        float2 a2 = s[IDX(tid + 256)];
        float2 a3 = s[IDX(tid + 384)];
        float2 s02 = make_float2(a0.x + a2.x, a0.y + a2.y);
        float2 d02 = make_float2(a0.x - a2.x, a0.y - a2.y);
        float2 s13 = make_float2(a1.x + a3.x, a1.y + a3.y);
        float2 d13 = make_float2(a1.x - a3.x, a1.y - a3.y);
        float2 A0 = make_float2(s02.x + s13.x, s02.y + s13.y);
        float2 A2 = make_float2(s02.x - s13.x, s02.y - s13.y);
        float2 A1, A3;
        if (INV > 0) {   // inverse: +i on d13 for A1
            A1 = make_float2(d02.x - d13.y, d02.y + d13.x);
            A3 = make_float2(d02.x + d13.y, d02.y - d13.x);
        } else {         // forward: -i on d13 for A1
            A1 = make_float2(d02.x + d13.y, d02.y - d13.x);
            A3 = make_float2(d02.x - d13.y, d02.y + d13.x);
        }
        float2 w1 = tw[pb];
        float2 w2 = tw[(2 * pb) & 511];
        float2 w3 = tw[(3 * pb) & 511];
        if (INV > 0) { A1 = cmul_inv(A1, w1); A2 = cmul_inv(A2, w2); A3 = cmul_inv(A3, w3); }
        else         { A1 = cmul_fwd(A1, w1); A2 = cmul_fwd(A2, w2); A3 = cmul_fwd(A3, w3); }
        int o = q + 4 * pb;
        d[IDX(o)]           = A0;
        d[IDX(o + str)]     = A1;
        d[IDX(o + 2 * str)] = A2;
        d[IDX(o + 3 * str)] = A3;
        __syncthreads();
        float2* tmp = s; s = d; d = tmp;
        str <<= 2;
    }
    // final radix-2, str = 256, twiddle = 1
    #pragma unroll
    for (int tt = 0; tt < 2; tt++) {
        int t = tid + tt * 128;
        float2 a = s[IDX(t)], b = s[IDX(t + 256)];
        d[IDX(t)]       = make_float2(a.x + b.x, a.y + b.y);
        d[IDX(t + 256)] = make_float2(a.x - b.x, a.y - b.y);
    }
    __syncthreads();
    return d;   // always == y (4 swaps + final)
}

__global__ __launch_bounds__(128) void k_frames(const float* __restrict__ noise) {
    __shared__ float2 bufA[FFTBUF], bufB[FFTBUF];
    __shared__ float2 FC[513];
    __shared__ float  sA[513];
    __shared__ float2 twS[512];
    __shared__ float  winS[1024];
    int tid = threadIdx.x, b = blockIdx.x;
    const float s512 = 1.0f / 512.0f;

    for (int i = tid; i < 512; i += 128) twS[i] = g_tw512[i];
    for (int i = tid; i < 1024; i += 128) winS[i] = g_win[i];
    for (int k = tid; k <= 512; k += 128) sA[k] = g_envperT[(size_t)b * NB + k];
    __syncthreads();

    // ---- min-phase: irfft of real log-amp (packed complex-512) ----
    for (int k = tid; k < 512; k += 128) {
        float u = sA[k], v = sA[512 - k];
        float2 tw = g_tw1024[k];
        float a  = 0.5f * (u + v);
        float dr = 0.5f * (u - v);
        bufA[IDX(k)] = make_float2(a - dr * tw.y, dr * tw.x);
    }
    __syncthreads();
    float2* z = fft512<1>(bufA, bufB, twS, tid);       // cepstrum pairs (unscaled)
    for (int n = tid; n < 512; n += 128) {             // fold + pack (1/512 folded in)
        float2 zv = z[IDX(n)];
        float2 w;
        if (n == 0)        w = make_float2(zv.x * s512, 2.0f * zv.y * s512);
        else if (n < 256)  w = make_float2(2.0f * zv.x * s512, 2.0f * zv.y * s512);
        else if (n == 256) w = make_float2(zv.x * s512, 0.0f);
        else               w = make_float2(0.0f, 0.0f);
        bufA[IDX(n)] = w;
    }
    __syncthreads();
    float2* W = fft512<-1>(bufA, bufB, twS, tid);      // rfft(folded cep) packed
    for (int k = tid; k <= 512; k += 128) {            // unpack H, F = exp(H)
        float2 u = W[IDX(k & 511)], v = W[IDX((512 - k) & 511)];
        float2 tw = g_tw1024[k];
        float ar = 0.5f * (u.x + v.x), ai = 0.5f * (u.y - v.y);
        float dr = u.x - v.x, di = u.y + v.y;
        float er = 0.5f * di, ei = -0.5f * dr;
        float hr = ar + er * tw.x + ei * tw.y;
        float hi = ai + ei * tw.x - er * tw.y;
        float m = expf(hr);
        FC[k] = make_float2(m * cosf(hi), m * sinf(hi));
    }
    for (int k = tid; k <= 512; k += 128) sA[k] = g_envnoiT[(size_t)b * NB + k];
    __syncthreads();

    // ---- pulse frame rfft, multiply by min-phase F ----
    for (int n = tid; n < 512; n += 128) {
        int j0 = 2 * n, j1 = 2 * n + 1;
        float p0 = g_pulse[reflect_idx(b * 256 + j0 - 256)] * winS[j0];
        float p1 = g_pulse[reflect_idx(b * 256 + j1 - 256)] * winS[j1];
        bufA[IDX(n)] = make_float2(p0, p1);
    }
    __syncthreads();
    float2* Zp = fft512<-1>(bufA, bufB, twS, tid);
    for (int k = tid; k <= 512; k += 128) {
        float2 u = Zp[IDX(k & 511)], v = Zp[IDX((512 - k) & 511)];
        float2 tw = g_tw1024[k];
        float ar = 0.5f * (u.x + v.x), ai = 0.5f * (u.y - v.y);
        float dr = u.x - v.x, di = u.y + v.y;
        float er = 0.5f * di, ei = -0.5f * dr;
        float sr = ar + er * tw.x + ei * tw.y;
        float si = ai + ei * tw.x - er * tw.y;
        float2 f = FC[k];
        FC[k] = make_float2(sr * f.x - si * f.y, sr * f.y + si * f.x);
    }
    __syncthreads();

    // ---- noise frame rfft, multiply by env, accumulate ----
    for (int n = tid; n < 512; n += 128) {
        int j0 = 2 * n, j1 = 2 * n + 1;
        float p0 = noise[reflect_idx(b * 256 + j0 - 256)] * winS[j0];
        float p1 = noise[reflect_idx(b * 256 + j1 - 256)] * winS[j1];
        bufA[IDX(n)] = make_float2(p0, p1);
    }
    __syncthreads();
    float2* Zn = fft512<-1>(bufA, bufB, twS, tid);
    for (int k = tid; k <= 512; k += 128) {
        float2 u = Zn[IDX(k & 511)], v = Zn[IDX((512 - k) & 511)];
        float2 tw = g_tw1024[k];
        float ar = 0.5f * (u.x + v.x), ai = 0.5f * (u.y - v.y);
        float dr = u.x - v.x, di = u.y + v.y;
        float er = 0.5f * di, ei = -0.5f * dr;
        float sr = ar + er * tw.x + ei * tw.y;
        float si = ai + ei * tw.x - er * tw.y;
        float e = sA[k];
        float2 c = FC[k];
        FC[k] = make_float2(c.x + sr * e, c.y + si * e);
    }
    __syncthreads();

    // ---- irfft(C) -> windowed frame ----
    for (int k = tid; k < 512; k += 128) {
        float2 u = FC[k], v = FC[512 - k];
        float2 tw = g_tw1024[k];
        float xr = 0.5f * (u.x + v.x), xi = 0.5f * (u.y - v.y);
        float dr = 0.5f * (u.x - v.x), di = 0.5f * (u.y + v.y);
        float tr = dr * tw.x - di * tw.y;
        float ti = dr * tw.y + di * tw.x;
        bufA[IDX(k)] = make_float2(xr - ti, xi + tr);
    }
    __syncthreads();
    float2* zz = fft512<1>(bufA, bufB, twS, tid);
    float* fr = g_frames + (size_t)b * 1024;
    for (int n = tid; n < 512; n += 128) {
        float2 zv = zz[IDX(n)];
        fr[2 * n]     = zv.x * s512 * winS[2 * n];
        fr[2 * n + 1] = zv.y * s512 * winS[2 * n + 1];
    }
}

__global__ void k_ola(float* __restrict__ out) {
    int m = blockIdx.x * 256 + threadIdx.x;
    if (m >= OUTLEN) return;
    int q = m + 512;
    int imin = (q > 1023) ? ((q - 1023 + 255) >> 8) : 0;
    int imax = min(q >> 8, NFR - 1);
    float sig = 0.0f, ws = 0.0f;
    for (int i = imin; i <= imax; i++) {
        int j = q - (i << 8);
        sig += g_frames[(size_t)i * 1024 + j];
        float w = g_win[j];
        ws += w * w;
    }
    out[m] = sig / fmaxf(ws, 1e-11f);
}

extern "C" void kernel_launch(void* const* d_in, const int* in_sizes, int n_in,
                              void* d_out, int out_size) {
    const float* log_f0 = (const float*)d_in[0];
    const float* env_noi = (const float*)d_in[1];
    const float* env_per = (const float*)d_in[2];
    const float* noise = (const float*)d_in[3];
    float* out = (float*)d_out;

    float* envnoiT; cudaGetSymbolAddress((void**)&envnoiT, g_envnoiT);
    float* envperT; cudaGetSymbolAddress((void**)&envperT, g_envperT);

    k_init<<<8, 128>>>();
    dim3 tb(32, 8), tg(NFR / 32, (NB + 31) / 32);
    k_transpose<<<tg, tb>>>(env_noi, envnoiT, 1);
    k_transpose<<<tg, tb>>>(env_per, envperT, 0);
    k_scan_up<<<NBLK, 512>>>(log_f0);
    k_scan_mid<<<1, 512>>>();
    k_scan_down<<<NBLK, 512>>>(log_f0);
    k_frames<<<NFR, 128>>>(noise);
    k_ola<<<(OUTLEN + 255) / 256, 256>>>(out);
}

// round 14
// speedup vs baseline: 1.1472x; 1.1387x over previous
#include <cuda_runtime.h>
#include <math.h>

#define NFFT   1024
#define HOP    256
#define NFR    16384
#define NB     513
#define LX     4194304
#define OUTLEN 4194048
#define SCAN_M 4096
#define NBLK   1024

__device__ float  g_pulse[LX];
__device__ float  g_envnoiT[(size_t)NFR * NB];
__device__ float  g_envperT[(size_t)NFR * NB];
__device__ float  g_frames[(size_t)NFR * NFFT];
__device__ float  g_bsum[NBLK];
__device__ float  g_bpref[NBLK];
__device__ float2 g_tw512[512];     // e^{+2pi i k/512}
__device__ float2 g_tw1024[513];
__device__ float  g_win[NFFT];

__global__ void k_init() {
    int i = blockIdx.x * blockDim.x + threadIdx.x;
    if (i < 512) {
        double th = 2.0 * 3.14159265358979323846 * (double)i / 512.0;
        g_tw512[i] = make_float2((float)cos(th), (float)sin(th));
    }
    if (i < 513) {
        double th = 2.0 * 3.14159265358979323846 * (double)i / 1024.0;
        g_tw1024[i] = make_float2((float)cos(th), (float)sin(th));
    }
    if (i < NFFT) {
        float ang = __fmul_rn(__fmul_rn(6.28318530717958647692f, (float)i), 0.0009765625f);
        g_win[i] = 0.5f * (1.0f - cosf(ang));
    }
}

// both transposes in one launch: z=0 -> env_noi (with exp), z=1 -> env_per
__global__ void k_transpose2(const float* __restrict__ in0, const float* __restrict__ in1,
                             float* __restrict__ out0, float* __restrict__ out1) {
    __shared__ float tile[32][33];
    int which = blockIdx.z;
    const float* in = which ? in1 : in0;
    float* out      = which ? out1 : out0;
    int doexp = (which == 0);
    int tx = threadIdx.x, ty = threadIdx.y;
    int t0 = blockIdx.x * 32, k0 = blockIdx.y * 32;
    for (int r = ty; r < 32; r += 8) {
        int k = k0 + r;
        tile[r][tx] = (k < NB) ? in[(size_t)k * NFR + t0 + tx] : 0.0f;
    }
    __syncthreads();
    for (int r = ty; r < 32; r += 8) {
        int t = t0 + r, k = k0 + tx;
        if (k < NB) {
            float v = tile[tx][r];
            out[(size_t)t * NB + k] = doexp ? expf(v) : v;
        }
    }
}

__device__ __forceinline__ float f0_up_val(const float* __restrict__ lf, int i) {
    float fi  = (float)i;
    float pos = __fmul_rn(__fadd_rn(fi, 0.5f), 0.00390625f);
    pos = __fsub_rn(pos, 0.5f);
    pos = fminf(fmaxf(pos, 0.0f), 16383.0f);
    float fl  = floorf(pos);
    int lo = (int)fl;
    int hi = min(lo + 1, NFR - 1);
    float frac = __fsub_rn(pos, fl);
    float a = expf(__ldg(lf + lo));
    float b = expf(__ldg(lf + hi));
    return __fadd_rn(__fmul_rn(a, __fsub_rn(1.0f, frac)), __fmul_rn(b, frac));
}

#define LVOFF(k)  (SCAN_M - (SCAN_M >> ((k) - 1)))
#define LVOFFM(k) (NBLK - (NBLK >> ((k) - 1)))

__device__ __forceinline__ void upsweep4096(const float* sx, float* slev, int tid) {
    for (int i = tid; i < 2048; i += 512) slev[i] = sx[2 * i] + sx[2 * i + 1];
    __syncthreads();
    for (int k = 2; k <= 12; k++) {
        int len = SCAN_M >> k;
        int off = LVOFF(k), offp = LVOFF(k - 1);
        for (int i = tid; i < len; i += 512)
            slev[off + i] = slev[offp + 2 * i] + slev[offp + 2 * i + 1];
        __syncthreads();
    }
}

__global__ __launch_bounds__(512) void k_scan_up(const float* __restrict__ lf) {
    __shared__ float sx[SCAN_M];
    __shared__ float slev[SCAN_M - 1];
    int tid = threadIdx.x, base = blockIdx.x * SCAN_M;
    for (int i = tid; i < SCAN_M; i += 512) sx[i] = f0_up_val(lf, base + i);
    __syncthreads();
    upsweep4096(sx, slev, tid);
    if (tid == 0) g_bsum[blockIdx.x] = slev[SCAN_M - 2];
}

__global__ __launch_bounds__(512) void k_scan_mid() {
    __shared__ float sx[NBLK];
    __shared__ float slev[NBLK - 1];
    int tid = threadIdx.x;
    for (int i = tid; i < NBLK; i += 512) sx[i] = g_bsum[i];
    __syncthreads();
    for (int i = tid; i < 512; i += 512) slev[i] = sx[2 * i] + sx[2 * i + 1];
    __syncthreads();
    for (int k = 2; k <= 10; k++) {
        int len = NBLK >> k;
        int off = LVOFFM(k), offp = LVOFFM(k - 1);
        for (int i = tid; i < len; i += 512)
            slev[off + i] = slev[offp + 2 * i] + slev[offp + 2 * i + 1];
        __syncthreads();
    }
    for (int k = 9; k >= 1; k--) {
        int len = NBLK >> k;
        int off = LVOFFM(k), offn = LVOFFM(k + 1);
        for (int i = tid; i < len; i += 512) {
            float v;
            if (i & 1)      v = slev[offn + ((i - 1) >> 1)];
            else if (i)     v = slev[offn + (i >> 1) - 1] + slev[off + i];
            else            v = slev[off];
            slev[off + i] = v;
        }
        __syncthreads();
    }
    for (int i = tid; i < NBLK; i += 512) {
        float v;
        if (i & 1)      v = slev[(i - 1) >> 1];
        else if (i)     v = slev[(i >> 1) - 1] + sx[i];
        else            v = sx[0];
        g_bpref[i] = v;
    }
}

// scan_down + pulse fused
__global__ __launch_bounds__(512) void k_scan_down(const float* __restrict__ lf) {
    __shared__ float sx[SCAN_M];
    __shared__ float slev[SCAN_M - 1];
    int tid = threadIdx.x, b = blockIdx.x, base = b * SCAN_M;
    float carry = (b == 0) ? 0.0f : g_bpref[b - 1];
    for (int i = tid; i < SCAN_M; i += 512) sx[i] = f0_up_val(lf, base + i);
    __syncthreads();
    upsweep4096(sx, slev, tid);
    if (tid == 0) slev[SCAN_M - 2] = g_bpref[b];
    __syncthreads();
    for (int k = 11; k >= 1; k--) {
        int len = SCAN_M >> k;
        int off = LVOFF(k), offn = LVOFF(k + 1);
        for (int i = tid; i < len; i += 512) {
            float v;
            if (i & 1)      v = slev[offn + ((i - 1) >> 1)];
            else if (i)     v = slev[offn + (i >> 1) - 1] + slev[off + i];
            else            v = b ? (carry + slev[off]) : slev[off];
            slev[off + i] = v;
        }
        __syncthreads();
    }
    for (int i = tid; i < SCAN_M; i += 512) {
        float vi;
        if (i & 1)      vi = slev[(i - 1) >> 1];
        else if (i)     vi = slev[(i >> 1) - 1] + sx[i];
        else            vi = b ? (carry + sx[0]) : sx[0];
        float vip;
        int j = i + 1;
        if (j < SCAN_M) {
            if (j & 1)  vip = slev[(j - 1) >> 1];
            else        vip = slev[(j >> 1) - 1] + sx[j];
        } else if (b < NBLK - 1) {
            vip = g_bpref[b] + f0_up_val(lf, base + SCAN_M);
        } else {
            vip = f0_up_val(lf, 0);
        }
        float ph0 = vi / 24000.0f;  float sw0 = __fsub_rn(ph0, truncf(ph0));
        float ph1 = vip / 24000.0f; float sw1 = __fsub_rn(ph1, truncf(ph1));
        g_pulse[base + i] = __fadd_rn(__fsub_rn(sw0, sw1), sx[i] / 24000.0f);
    }
}

__device__ __forceinline__ int reflect_idx(int p) {
    if (p < 0) return -p;
    if (p >= LX) return 2 * LX - 2 - p;
    return p;
}

// ---------------- radix-4 Stockham FFT-512, 128 threads, gmem twiddles ----------------
#define IDX(a) ((a) + ((a) >> 3))
#define FFTBUF 576

__device__ __forceinline__ float2 cmul_fwd(float2 a, float2 w) {
    return make_float2(a.x * w.x + a.y * w.y, a.y * w.x - a.x * w.y);
}
__device__ __forceinline__ float2 cmul_inv(float2 a, float2 w) {
    return make_float2(a.x * w.x - a.y * w.y, a.y * w.x + a.x * w.y);
}

template <int INV>
__device__ float2* fft512(float2* x, float2* y, int tid) {
    float2* s = x; float2* d = y;
    int str = 1;
    #pragma unroll
    for (int stg = 0; stg < 4; stg++) {
        int q  = tid & (str - 1);
        int pb = tid - q;
        float2 a0 = s[IDX(tid)];
        float2 a1 = s[IDX(tid + 128)];
        float2 a2 = s[IDX(tid + 256)];
        float2 a3 = s[IDX(tid + 384)];
        float2 w1 = __ldg(&g_tw512[pb]);
        float2 w2 = __ldg(&g_tw512[(2 * pb) & 511]);
        float2 w3 = __ldg(&g_tw512[(3 * pb) & 511]);
        float2 s02 = make_float2(a0.x + a2.x, a0.y + a2.y);
        float2 d02 = make_float2(a0.x - a2.x, a0.y - a2.y);
        float2 s13 = make_float2(a1.x + a3.x, a1.y + a3.y);
        float2 d13 = make_float2(a1.x - a3.x, a1.y - a3.y);
        float2 A0 = make_float2(s02.x + s13.x, s02.y + s13.y);
        float2 A2 = make_float2(s02.x - s13.x, s02.y - s13.y);
        float2 A1, A3;
        if (INV > 0) {
            A1 = make_float2(d02.x - d13.y, d02.y + d13.x);
            A3 = make_float2(d02.x + d13.y, d02.y - d13.x);
        } else {
            A1 = make_float2(d02.x + d13.y, d02.y - d13.x);
            A3 = make_float2(d02.x - d13.y, d02.y + d13.x);
        }
        if (INV > 0) { A1 = cmul_inv(A1, w1); A2 = cmul_inv(A2, w2); A3 = cmul_inv(A3, w3); }
        else         { A1 = cmul_fwd(A1, w1); A2 = cmul_fwd(A2, w2); A3 = cmul_fwd(A3, w3); }
        int o = q + 4 * pb;
        d[IDX(o)]           = A0;
        d[IDX(o + str)]     = A1;
        d[IDX(o + 2 * str)] = A2;
        d[IDX(o + 3 * str)] = A3;
        __syncthreads();
        float2* tmp = s; s = d; d = tmp;
        str <<= 2;
    }
    #pragma unroll
    for (int tt = 0; tt < 2; tt++) {
        int t = tid + tt * 128;
        float2 a = s[IDX(t)], b = s[IDX(t + 256)];
        d[IDX(t)]       = make_float2(a.x + b.x, a.y + b.y);
        d[IDX(t + 256)] = make_float2(a.x - b.x, a.y - b.y);
    }
    __syncthreads();
    return d;
}

__global__ __launch_bounds__(128) void k_frames(const float* __restrict__ noise) {
    __shared__ float2 bufA[FFTBUF], bufB[FFTBUF];
    __shared__ float2 FC[513];
    __shared__ float  sP[513];
    __shared__ float  sN[513];
    int tid = threadIdx.x, b = blockIdx.x;
    const float s512 = 1.0f / 512.0f;

    // ---- prefetch everything up front (max MLP) ----
    float4 pu[2], no[2], wv[2];
    {
        int base = b * 256 - 256;
        wv[0] = *(const float4*)(g_win + 4 * tid);
        wv[1] = *(const float4*)(g_win + 4 * (tid + 128));
        if (b >= 1 && b <= NFR - 3) {
            const float4* pp = (const float4*)(g_pulse + base);
            const float4* nn = (const float4*)(noise + base);
            pu[0] = pp[tid];       no[0] = nn[tid];
            pu[1] = pp[tid + 128]; no[1] = nn[tid + 128];
        } else {
            #pragma unroll
            for (int t = 0; t < 2; t++) {
                float tp[4], tn[4];
                #pragma unroll
                for (int c = 0; c < 4; c++) {
                    int idx = reflect_idx(base + (tid + t * 128) * 4 + c);
                    tp[c] = g_pulse[idx];
                    tn[c] = noise[idx];
                }
                pu[t] = make_float4(tp[0], tp[1], tp[2], tp[3]);
                no[t] = make_float4(tn[0], tn[1], tn[2], tn[3]);
            }
        }
        const float* ep = g_envperT + (size_t)b * NB;
        const float* en = g_envnoiT + (size_t)b * NB;
        for (int k = tid; k <= 512; k += 128) { sP[k] = __ldg(ep + k); sN[k] = __ldg(en + k); }
    }
    __syncthreads();

    // ---- min-phase: irfft of real log-amp (packed complex-512) ----
    for (int k = tid; k < 512; k += 128) {
        float u = sP[k], v = sP[512 - k];
        float2 tw = __ldg(&g_tw1024[k]);
        float a  = 0.5f * (u + v);
        float dr = 0.5f * (u - v);
        bufA[IDX(k)] = make_float2(a - dr * tw.y, dr * tw.x);
    }
    __syncthreads();
    float2* z = fft512<1>(bufA, bufB, tid);
    for (int n = tid; n < 512; n += 128) {
        float2 zv = z[IDX(n)];
        float2 w;
        if (n == 0)        w = make_float2(zv.x * s512, 2.0f * zv.y * s512);
        else if (n < 256)  w = make_float2(2.0f * zv.x * s512, 2.0f * zv.y * s512);
        else if (n == 256) w = make_float2(zv.x * s512, 0.0f);
        else               w = make_float2(0.0f, 0.0f);
        bufA[IDX(n)] = w;
    }
    __syncthreads();
    float2* W = fft512<-1>(bufA, bufB, tid);
    for (int k = tid; k <= 512; k += 128) {
        float2 u = W[IDX(k & 511)], v = W[IDX((512 - k) & 511)];
        float2 tw = __ldg(&g_tw1024[k]);
        float ar = 0.5f * (u.x + v.x), ai = 0.5f * (u.y - v.y);
        float dr = u.x - v.x, di = u.y + v.y;
        float er = 0.5f * di, ei = -0.5f * dr;
        float hr = ar + er * tw.x + ei * tw.y;
        float hi = ai + ei * tw.x - er * tw.y;
        float m = expf(hr);
        FC[k] = make_float2(m * cosf(hi), m * sinf(hi));
    }
    __syncthreads();

    // ---- pulse frame rfft (windowed from regs), multiply by min-phase F ----
    bufA[IDX(2 * tid)]       = make_float2(pu[0].x * wv[0].x, pu[0].y * wv[0].y);
    bufA[IDX(2 * tid + 1)]   = make_float2(pu[0].z * wv[0].z, pu[0].w * wv[0].w);
    bufA[IDX(2 * tid + 256)] = make_float2(pu[1].x * wv[1].x, pu[1].y * wv[1].y);
    bufA[IDX(2 * tid + 257)] = make_float2(pu[1].z * wv[1].z, pu[1].w * wv[1].w);
    __syncthreads();
    float2* Zp = fft512<-1>(bufA, bufB, tid);
    for (int k = tid; k <= 512; k += 128) {
        float2 u = Zp[IDX(k & 511)], v = Zp[IDX((512 - k) & 511)];
        float2 tw = __ldg(&g_tw1024[k]);
        float ar = 0.5f * (u.x + v.x), ai = 0.5f * (u.y - v.y);
        float dr = u.x - v.x, di = u.y + v.y;
        float er = 0.5f * di, ei = -0.5f * dr;
        float sr = ar + er * tw.x + ei * tw.y;
        float si = ai + ei * tw.x - er * tw.y;
        float2 f = FC[k];
        FC[k] = make_float2(sr * f.x - si * f.y, sr * f.y + si * f.x);
    }
    __syncthreads();

    // ---- noise frame rfft (windowed from regs), multiply by env, accumulate ----
    bufA[IDX(2 * tid)]       = make_float2(no[0].x * wv[0].x, no[0].y * wv[0].y);
    bufA[IDX(2 * tid + 1)]   = make_float2(no[0].z * wv[0].z, no[0].w * wv[0].w);
    bufA[IDX(2 * tid + 256)] = make_float2(no[1].x * wv[1].x, no[1].y * wv[1].y);
    bufA[IDX(2 * tid + 257)] = make_float2(no[1].z * wv[1].z, no[1].w * wv[1].w);
    __syncthreads();
    float2* Zn = fft512<-1>(bufA, bufB, tid);
    for (int k = tid; k <= 512; k += 128) {
        float2 u = Zn[IDX(k & 511)], v = Zn[IDX((512 - k) & 511)];
        float2 tw = __ldg(&g_tw1024[k]);
        float ar = 0.5f * (u.x + v.x), ai = 0.5f * (u.y - v.y);
        float dr = u.x - v.x, di = u.y + v.y;
        float er = 0.5f * di, ei = -0.5f * dr;
        float sr = ar + er * tw.x + ei * tw.y;
        float si = ai + ei * tw.x - er * tw.y;
        float e = sN[k];
        float2 c = FC[k];
        FC[k] = make_float2(c.x + sr * e, c.y + si * e);
    }
    __syncthreads();

    // ---- irfft(C) -> windowed frame (float2 stores) ----
    for (int k = tid; k < 512; k += 128) {
        float2 u = FC[k], v = FC[512 - k];
        float2 tw = __ldg(&g_tw1024[k]);
        float xr = 0.5f * (u.x + v.x), xi = 0.5f * (u.y - v.y);
        float dr = 0.5f * (u.x - v.x), di = 0.5f * (u.y + v.y);
        float tr = dr * tw.x - di * tw.y;
        float ti = dr * tw.y + di * tw.x;
        bufA[IDX(k)] = make_float2(xr - ti, xi + tr);
    }
    __syncthreads();
    float2* zz = fft512<1>(bufA, bufB, tid);
    float2* fr2 = (float2*)(g_frames + (size_t)b * 1024);
    const float2* wp = (const float2*)g_win;
    for (int n = tid; n < 512; n += 128) {
        float2 zv = zz[IDX(n)];
        float2 w = __ldg(wp + n);
        fr2[n] = make_float2(zv.x * s512 * w.x, zv.y * s512 * w.y);
    }
}

__global__ void k_ola(float* __restrict__ out) {
    int m = blockIdx.x * 256 + threadIdx.x;
    if (m >= OUTLEN) return;
    int q = m + 512;
    int imin = (q > 1023) ? ((q - 1023 + 255) >> 8) : 0;
    int imax = min(q >> 8, NFR - 1);
    float sig = 0.0f, ws = 0.0f;
    for (int i = imin; i <= imax; i++) {
        int j = q - (i << 8);
        sig += g_frames[(size_t)i * 1024 + j];
        float w = __ldg(g_win + j);
        ws += w * w;
    }
    out[m] = sig / fmaxf(ws, 1e-11f);
}

extern "C" void kernel_launch(void* const* d_in, const int* in_sizes, int n_in,
                              void* d_out, int out_size) {
    const float* log_f0 = (const float*)d_in[0];
    const float* env_noi = (const float*)d_in[1];
    const float* env_per = (const float*)d_in[2];
    const float* noise = (const float*)d_in[3];
    float* out = (float*)d_out;

    float* envnoiT; cudaGetSymbolAddress((void**)&envnoiT, g_envnoiT);
    float* envperT; cudaGetSymbolAddress((void**)&envperT, g_envperT);

    k_init<<<8, 128>>>();
    dim3 tb(32, 8), tg(NFR / 32, (NB + 31) / 32, 2);
    k_transpose2<<<tg, tb>>>(env_noi, env_per, envnoiT, envperT);
    k_scan_up<<<NBLK, 512>>>(log_f0);
    k_scan_mid<<<1, 512>>>();
    k_scan_down<<<NBLK, 512>>>(log_f0);
    k_frames<<<NFR, 128>>>(noise);
    k_ola<<<(OUTLEN + 255) / 256, 256>>>(out);
}

// round 16
// speedup vs baseline: 1.1909x; 1.0381x over previous
#include <cuda_runtime.h>
#include <math.h>

#define NFFT   1024
#define HOP    256
#define NFR    16384
#define NB     513
#define LX     4194304
#define OUTLEN 4194048
#define SCAN_M 4096
#define NBLK   1024

__device__ float  g_pulse[LX];
__device__ float  g_envnoiT[(size_t)NFR * NB];
__device__ float  g_envperT[(size_t)NFR * NB];
__device__ float  g_frames[(size_t)NFR * NFFT];
__device__ float  g_bsum[NBLK];
__device__ float  g_bpref[NBLK];
__device__ float2 g_tw512[512];      // e^{+2pi i k/512}
__device__ float2 g_twfull[1024];    // e^{+2pi i k/1024}
__device__ float2 g_tw1024[513];
__device__ float  g_win[NFFT];

__global__ void k_init() {
    int i = blockIdx.x * blockDim.x + threadIdx.x;
    if (i < 512) {
        double th = 2.0 * 3.14159265358979323846 * (double)i / 512.0;
        g_tw512[i] = make_float2((float)cos(th), (float)sin(th));
    }
    if (i < 1024) {
        double th = 2.0 * 3.14159265358979323846 * (double)i / 1024.0;
        g_twfull[i] = make_float2((float)cos(th), (float)sin(th));
    }
    if (i < 513) {
        double th = 2.0 * 3.14159265358979323846 * (double)i / 1024.0;
        g_tw1024[i] = make_float2((float)cos(th), (float)sin(th));
    }
    if (i < NFFT) {
        float ang = __fmul_rn(__fmul_rn(6.28318530717958647692f, (float)i), 0.0009765625f);
        g_win[i] = 0.5f * (1.0f - cosf(ang));
    }
}

__global__ void k_transpose2(const float* __restrict__ in0, const float* __restrict__ in1,
                             float* __restrict__ out0, float* __restrict__ out1) {
    __shared__ float tile[32][33];
    int which = blockIdx.z;
    const float* in = which ? in1 : in0;
    float* out      = which ? out1 : out0;
    int doexp = (which == 0);
    int tx = threadIdx.x, ty = threadIdx.y;
    int t0 = blockIdx.x * 32, k0 = blockIdx.y * 32;
    for (int r = ty; r < 32; r += 8) {
        int k = k0 + r;
        tile[r][tx] = (k < NB) ? in[(size_t)k * NFR + t0 + tx] : 0.0f;
    }
    __syncthreads();
    for (int r = ty; r < 32; r += 8) {
        int t = t0 + r, k = k0 + tx;
        if (k < NB) {
            float v = tile[tx][r];
            out[(size_t)t * NB + k] = doexp ? expf(v) : v;
        }
    }
}

__device__ __forceinline__ float f0_up_val(const float* __restrict__ lf, int i) {
    float fi  = (float)i;
    float pos = __fmul_rn(__fadd_rn(fi, 0.5f), 0.00390625f);
    pos = __fsub_rn(pos, 0.5f);
    pos = fminf(fmaxf(pos, 0.0f), 16383.0f);
    float fl  = floorf(pos);
    int lo = (int)fl;
    int hi = min(lo + 1, NFR - 1);
    float frac = __fsub_rn(pos, fl);
    float a = expf(__ldg(lf + lo));
    float b = expf(__ldg(lf + hi));
    return __fadd_rn(__fmul_rn(a, __fsub_rn(1.0f, frac)), __fmul_rn(b, frac));
}

#define LVOFF(k)  (SCAN_M - (SCAN_M >> ((k) - 1)))
#define LVOFFM(k) (NBLK - (NBLK >> ((k) - 1)))

__device__ __forceinline__ void upsweep4096(const float* sx, float* slev, int tid) {
    for (int i = tid; i < 2048; i += 512) slev[i] = sx[2 * i] + sx[2 * i + 1];
    __syncthreads();
    for (int k = 2; k <= 12; k++) {
        int len = SCAN_M >> k;
        int off = LVOFF(k), offp = LVOFF(k - 1);
        for (int i = tid; i < len; i += 512)
            slev[off + i] = slev[offp + 2 * i] + slev[offp + 2 * i + 1];
        __syncthreads();
    }
}

__global__ __launch_bounds__(512) void k_scan_up(const float* __restrict__ lf) {
    __shared__ float sx[SCAN_M];
    __shared__ float slev[SCAN_M - 1];
    int tid = threadIdx.x, base = blockIdx.x * SCAN_M;
    for (int i = tid; i < SCAN_M; i += 512) sx[i] = f0_up_val(lf, base + i);
    __syncthreads();
    upsweep4096(sx, slev, tid);
    if (tid == 0) g_bsum[blockIdx.x] = slev[SCAN_M - 2];
}

__global__ __launch_bounds__(512) void k_scan_mid() {
    __shared__ float sx[NBLK];
    __shared__ float slev[NBLK - 1];
    int tid = threadIdx.x;
    for (int i = tid; i < NBLK; i += 512) sx[i] = g_bsum[i];
    __syncthreads();
    for (int i = tid; i < 512; i += 512) slev[i] = sx[2 * i] + sx[2 * i + 1];
    __syncthreads();
    for (int k = 2; k <= 10; k++) {
        int len = NBLK >> k;
        int off = LVOFFM(k), offp = LVOFFM(k - 1);
        for (int i = tid; i < len; i += 512)
            slev[off + i] = slev[offp + 2 * i] + slev[offp + 2 * i + 1];
        __syncthreads();
    }
    for (int k = 9; k >= 1; k--) {
        int len = NBLK >> k;
        int off = LVOFFM(k), offn = LVOFFM(k + 1);
        for (int i = tid; i < len; i += 512) {
            float v;
            if (i & 1)      v = slev[offn + ((i - 1) >> 1)];
            else if (i)     v = slev[offn + (i >> 1) - 1] + slev[off + i];
            else            v = slev[off];
            slev[off + i] = v;
        }
        __syncthreads();
    }
    for (int i = tid; i < NBLK; i += 512) {
        float v;
        if (i & 1)      v = slev[(i - 1) >> 1];
        else if (i)     v = slev[(i >> 1) - 1] + sx[i];
        else            v = sx[0];
        g_bpref[i] = v;
    }
}

__global__ __launch_bounds__(512) void k_scan_down(const float* __restrict__ lf) {
    __shared__ float sx[SCAN_M];
    __shared__ float slev[SCAN_M - 1];
    int tid = threadIdx.x, b = blockIdx.x, base = b * SCAN_M;
    float carry = (b == 0) ? 0.0f : g_bpref[b - 1];
    for (int i = tid; i < SCAN_M; i += 512) sx[i] = f0_up_val(lf, base + i);
    __syncthreads();
    upsweep4096(sx, slev, tid);
    if (tid == 0) slev[SCAN_M - 2] = g_bpref[b];
    __syncthreads();
    for (int k = 11; k >= 1; k--) {
        int len = SCAN_M >> k;
        int off = LVOFF(k), offn = LVOFF(k + 1);
        for (int i = tid; i < len; i += 512) {
            float v;
            if (i & 1)      v = slev[offn + ((i - 1) >> 1)];
            else if (i)     v = slev[offn + (i >> 1) - 1] + slev[off + i];
            else            v = b ? (carry + slev[off]) : slev[off];
            slev[off + i] = v;
        }
        __syncthreads();
    }
    for (int i = tid; i < SCAN_M; i += 512) {
        float vi;
        if (i & 1)      vi = slev[(i - 1) >> 1];
        else if (i)     vi = slev[(i >> 1) - 1] + sx[i];
        else            vi = b ? (carry + sx[0]) : sx[0];
        float vip;
        int j = i + 1;
        if (j < SCAN_M) {
            if (j & 1)  vip = slev[(j - 1) >> 1];
            else        vip = slev[(j >> 1) - 1] + sx[j];
        } else if (b < NBLK - 1) {
            vip = g_bpref[b] + f0_up_val(lf, base + SCAN_M);
        } else {
            vip = f0_up_val(lf, 0);
        }
        float ph0 = vi / 24000.0f;  float sw0 = __fsub_rn(ph0, truncf(ph0));
        float ph1 = vip / 24000.0f; float sw1 = __fsub_rn(ph1, truncf(ph1));
        g_pulse[base + i] = __fadd_rn(__fsub_rn(sw0, sw1), sx[i] / 24000.0f);
    }
}

__device__ __forceinline__ int reflect_idx(int p) {
    if (p < 0) return -p;
    if (p >= LX) return 2 * LX - 2 - p;
    return p;
}

#define IDX(a) ((a) + ((a) >> 3))
#define BUF512 576
#define BUF1024 1152

__device__ __forceinline__ float2 cmul_fwd(float2 a, float2 w) {  // a * e^{-i th}
    return make_float2(a.x * w.x + a.y * w.y, a.y * w.x - a.x * w.y);
}
__device__ __forceinline__ float2 cmul_inv(float2 a, float2 w) {  // a * e^{+i th}
    return make_float2(a.x * w.x - a.y * w.y, a.y * w.x + a.x * w.y);
}

// radix-4 Stockham FFT-512 (128 thr). Result in y.
template <int INV>
__device__ float2* fft512(float2* x, float2* y, int tid) {
    float2* s = x; float2* d = y;
    int str = 1;
    #pragma unroll
    for (int stg = 0; stg < 4; stg++) {
        int q  = tid & (str - 1);
        int pb = tid - q;
        float2 a0 = s[IDX(tid)];
        float2 a1 = s[IDX(tid + 128)];
        float2 a2 = s[IDX(tid + 256)];
        float2 a3 = s[IDX(tid + 384)];
        float2 w1 = __ldg(&g_tw512[pb]);
        float2 w2 = __ldg(&g_tw512[(2 * pb) & 511]);
        float2 w3 = __ldg(&g_tw512[(3 * pb) & 511]);
        float2 s02 = make_float2(a0.x + a2.x, a0.y + a2.y);
        float2 d02 = make_float2(a0.x - a2.x, a0.y - a2.y);
        float2 s13 = make_float2(a1.x + a3.x, a1.y + a3.y);
        float2 d13 = make_float2(a1.x - a3.x, a1.y - a3.y);
        float2 A0 = make_float2(s02.x + s13.x, s02.y + s13.y);
        float2 A2 = make_float2(s02.x - s13.x, s02.y - s13.y);
        float2 A1, A3;
        if (INV > 0) {
            A1 = make_float2(d02.x - d13.y, d02.y + d13.x);
            A3 = make_float2(d02.x + d13.y, d02.y - d13.x);
        } else {
            A1 = make_float2(d02.x + d13.y, d02.y - d13.x);
            A3 = make_float2(d02.x - d13.y, d02.y + d13.x);
        }
        if (INV > 0) { A1 = cmul_inv(A1, w1); A2 = cmul_inv(A2, w2); A3 = cmul_inv(A3, w3); }
        else         { A1 = cmul_fwd(A1, w1); A2 = cmul_fwd(A2, w2); A3 = cmul_fwd(A3, w3); }
        int o = q + 4 * pb;
        d[IDX(o)]           = A0;
        d[IDX(o + str)]     = A1;
        d[IDX(o + 2 * str)] = A2;
        d[IDX(o + 3 * str)] = A3;
        __syncthreads();
        float2* tmp = s; s = d; d = tmp;
        str <<= 2;
    }
    #pragma unroll
    for (int tt = 0; tt < 2; tt++) {
        int t = tid + tt * 128;
        float2 a = s[IDX(t)], b = s[IDX(t + 256)];
        d[IDX(t)]       = make_float2(a.x + b.x, a.y + b.y);
        d[IDX(t + 256)] = make_float2(a.x - b.x, a.y - b.y);
    }
    __syncthreads();
    return d;
}

// radix-4 Stockham complex FFT-1024 forward (128 thr, 2 butterflies/thr). Result in y.
__device__ float2* fft1024_fwd(float2* x, float2* y, int tid) {
    float2* s = x; float2* d = y;
    int str = 1;
    #pragma unroll
    for (int stg = 0; stg < 5; stg++) {
        #pragma unroll
        for (int tt = 0; tt < 2; tt++) {
            int t = tid + tt * 128;
            int q  = t & (str - 1);
            int pb = t - q;
            float2 a0 = s[IDX(t)];
            float2 a1 = s[IDX(t + 256)];
            float2 a2 = s[IDX(t + 512)];
            float2 a3 = s[IDX(t + 768)];
            float2 w1 = __ldg(&g_twfull[pb]);
            float2 w2 = __ldg(&g_twfull[(2 * pb) & 1023]);
            float2 w3 = __ldg(&g_twfull[(3 * pb) & 1023]);
            float2 s02 = make_float2(a0.x + a2.x, a0.y + a2.y);
            float2 d02 = make_float2(a0.x - a2.x, a0.y - a2.y);
            float2 s13 = make_float2(a1.x + a3.x, a1.y + a3.y);
            float2 d13 = make_float2(a1.x - a3.x, a1.y - a3.y);
            float2 A0 = make_float2(s02.x + s13.x, s02.y + s13.y);
            float2 A2 = make_float2(s02.x - s13.x, s02.y - s13.y);
            float2 A1 = make_float2(d02.x + d13.y, d02.y - d13.x);   // forward: -i
            float2 A3 = make_float2(d02.x - d13.y, d02.y + d13.x);
            A1 = cmul_fwd(A1, w1); A2 = cmul_fwd(A2, w2); A3 = cmul_fwd(A3, w3);
            int o = q + 4 * pb;
            d[IDX(o)]           = A0;
            d[IDX(o + str)]     = A1;
            d[IDX(o + 2 * str)] = A2;
            d[IDX(o + 3 * str)] = A3;
        }
        __syncthreads();
        float2* tmp = s; s = d; d = tmp;
        str <<= 2;
    }
    return s;
}

__global__ __launch_bounds__(128) void k_frames(const float* __restrict__ noise) {
    __shared__ float2 bigA[BUF1024];      // also hosts bufS1/bufS2 after Z moves to bigB
    __shared__ float2 bigB[BUF1024];
    __shared__ float2 FC[513];
    int tid = threadIdx.x, b = blockIdx.x;
    const float s512 = 1.0f / 512.0f;

    // ---- prefetch frame data (max MLP) and pack p + i*n into bigA ----
    {
        float4 pu[2], no[2], wv[2];
        int base = b * 256 - 256;
        wv[0] = *(const float4*)(g_win + 4 * tid);
        wv[1] = *(const float4*)(g_win + 4 * (tid + 128));
        if (b >= 1 && b <= NFR - 3) {
            const float4* pp = (const float4*)(g_pulse + base);
            const float4* nn = (const float4*)(noise + base);
            pu[0] = pp[tid];       no[0] = nn[tid];
            pu[1] = pp[tid + 128]; no[1] = nn[tid + 128];
        } else {
            #pragma unroll
            for (int t = 0; t < 2; t++) {
                float tp[4], tn[4];
                #pragma unroll
                for (int c = 0; c < 4; c++) {
                    int idx = reflect_idx(base + (tid + t * 128) * 4 + c);
                    tp[c] = g_pulse[idx];
                    tn[c] = noise[idx];
                }
                pu[t] = make_float4(tp[0], tp[1], tp[2], tp[3]);
                no[t] = make_float4(tn[0], tn[1], tn[2], tn[3]);
            }
        }
        #pragma unroll
        for (int t = 0; t < 2; t++) {
            int j = 4 * (tid + t * 128);
            float* pw = (float*)&pu[t]; float* nw = (float*)&no[t]; float* ww = (float*)&wv[t];
            #pragma unroll
            for (int c = 0; c < 4; c++)
                bigA[IDX(j + c)] = make_float2(pw[c] * ww[c], nw[c] * ww[c]);
        }
    }
    __syncthreads();

    // ---- one complex-1024 FFT: Z = rfft-pair of (pulse, noise) frames ----
    float2* Z = fft1024_fwd(bigA, bigB, tid);            // Z in bigB
    float2* bufS1 = bigA;                                 // reuse dead buffer
    float2* bufS2 = bigA + BUF512;

    // ---- min-phase: irfft of real log-amp (packed complex-512) ----
    const float* ep = g_envperT + (size_t)b * NB;
    for (int k = tid; k < 512; k += 128) {
        float u = __ldg(ep + k), v = __ldg(ep + 512 - k);
        float2 tw = __ldg(&g_tw1024[k]);
        float a  = 0.5f * (u + v);
        float dr = 0.5f * (u - v);
        bufS1[IDX(k)] = make_float2(a - dr * tw.y, dr * tw.x);
    }
    __syncthreads();
    float2* z = fft512<1>(bufS1, bufS2, tid);            // cepstrum pairs -> bufS2
    for (int n = tid; n < 512; n += 128) {
        float2 zv = z[IDX(n)];
        float2 w;
        if (n == 0)        w = make_float2(zv.x * s512, 2.0f * zv.y * s512);
        else if (n < 256)  w = make_float2(2.0f * zv.x * s512, 2.0f * zv.y * s512);
        else if (n == 256) w = make_float2(zv.x * s512, 0.0f);
        else               w = make_float2(0.0f, 0.0f);
        bufS1[IDX(n)] = w;
    }
    __syncthreads();
    float2* W = fft512<-1>(bufS1, bufS2, tid);           // rfft(folded cep) -> bufS2
    for (int k = tid; k <= 512; k += 128) {              // unpack H, F = exp(H)
        float2 u = W[IDX(k & 511)], v = W[IDX((512 - k) & 511)];
        float2 tw = __ldg(&g_tw1024[k]);
        float ar = 0.5f * (u.x + v.x), ai = 0.5f * (u.y - v.y);
        float dr = u.x - v.x, di = u.y + v.y;
        float er = 0.5f * di, ei = -0.5f * dr;
        float hr = ar + er * tw.x + ei * tw.y;
        float hi = ai + ei * tw.x - er * tw.y;
        float m = __expf(hr);
        float sh, ch; __sincosf(hi, &sh, &ch);
        FC[k] = make_float2(m * ch, m * sh);
    }
    __syncthreads();

    // ---- combine: C = Sp*F + Sn*env_noi (Sp,Sn from Z by Hermitian split) ----
    const float* en = g_envnoiT + (size_t)b * NB;
    for (int k = tid; k <= 512; k += 128) {
        float2 Zk = Z[IDX(k & 1023)];
        float2 Zm = Z[IDX((1024 - k) & 1023)];
        float spr = 0.5f * (Zk.x + Zm.x), spi = 0.5f * (Zk.y - Zm.y);
        float snr = 0.5f * (Zk.y + Zm.y), sni = 0.5f * (Zm.x - Zk.x);
        float2 f = FC[k];
        float e = __ldg(en + k);
        FC[k] = make_float2(spr * f.x - spi * f.y + snr * e,
                            spr * f.y + spi * f.x + sni * e);
    }
    __syncthreads();

    // ---- irfft(C) -> windowed frame ----
    for (int k = tid; k < 512; k += 128) {
        float2 u = FC[k], v = FC[512 - k];
        float2 tw = __ldg(&g_tw1024[k]);
        float xr = 0.5f * (u.x + v.x), xi = 0.5f * (u.y - v.y);
        float dr = 0.5f * (u.x - v.x), di = 0.5f * (u.y + v.y);
        float tr = dr * tw.x - di * tw.y;
        float ti = dr * tw.y + di * tw.x;
        bufS1[IDX(k)] = make_float2(xr - ti, xi + tr);
    }
    __syncthreads();
    float2* zz = fft512<1>(bufS1, bufS2, tid);
    float2* fr2 = (float2*)(g_frames + (size_t)b * 1024);
    const float2* wp = (const float2*)g_win;
    for (int n = tid; n < 512; n += 128) {
        float2 zv = zz[IDX(n)];
        float2 w = __ldg(wp + n);
        fr2[n] = make_float2(zv.x * s512 * w.x, zv.y * s512 * w.y);
    }
}

__global__ void k_ola(float* __restrict__ out) {
    int m = blockIdx.x * 256 + threadIdx.x;
    if (m >= OUTLEN) return;
    int q = m + 512;
    int imin = (q > 1023) ? ((q - 1023 + 255) >> 8) : 0;
    int imax = min(q >> 8, NFR - 1);
    float sig = 0.0f, ws = 0.0f;
    for (int i = imin; i <= imax; i++) {
        int j = q - (i << 8);
        sig += g_frames[(size_t)i * 1024 + j];
        float w = __ldg(g_win + j);
        ws += w * w;
    }
    out[m] = sig / fmaxf(ws, 1e-11f);
}

extern "C" void kernel_launch(void* const* d_in, const int* in_sizes, int n_in,
                              void* d_out, int out_size) {
    const float* log_f0 = (const float*)d_in[0];
    const float* env_noi = (const float*)d_in[1];
    const float* env_per = (const float*)d_in[2];
    const float* noise = (const float*)d_in[3];
    float* out = (float*)d_out;

    float* envnoiT; cudaGetSymbolAddress((void**)&envnoiT, g_envnoiT);
    float* envperT; cudaGetSymbolAddress((void**)&envperT, g_envperT);

    k_init<<<8, 128>>>();
    dim3 tb(32, 8), tg(NFR / 32, (NB + 31) / 32, 2);
    k_transpose2<<<tg, tb>>>(env_noi, env_per, envnoiT, envperT);
    k_scan_up<<<NBLK, 512>>>(log_f0);
    k_scan_mid<<<1, 512>>>();
    k_scan_down<<<NBLK, 512>>>(log_f0);
    k_frames<<<NFR, 128>>>(noise);
    k_ola<<<(OUTLEN + 255) / 256, 256>>>(out);
}